// round 12
// baseline (speedup 1.0000x reference)
#include <cuda_runtime.h>
#include <cuda_bf16.h>

typedef unsigned long long u64;

#define BATCH  128
#define IN_K   1024
#define OUT_N  1024
#define GMAX   16

#define OT     64     // output rows per block tile
#define KSPLIT 16     // k-splits
#define KC     (IN_K / KSPLIT)   // 64 k per block
#define KS     32     // k per shared stage
#define XPAD   36     // padded row stride (floats): conflict-free LDS.128
#define RPAD   65     // epilogue staging stride (64 cols + 1)

// split-K partial sums: [KSPLIT][BATCH][OUT_N]  (8 MB, static device scratch)
__device__ float g_scratch[KSPLIT * BATCH * OUT_N];

__device__ __forceinline__ u64 ffma2(u64 a, u64 b, u64 c) {
    u64 d;
    asm("fma.rn.f32x2 %0, %1, %2, %3;" : "=l"(d) : "l"(a), "l"(b), "l"(c));
    return d;
}

__device__ __forceinline__ float f32x2_hsum(u64 v) {
    float lo = __uint_as_float((unsigned)(v & 0xffffffffull));
    float hi = __uint_as_float((unsigned)(v >> 32));
    return lo + hi;
}

// ---------------------------------------------------------------------------
// Kernel A: partial GEMM. y_partial = x[:, k0:k0+KC] @ W[:, k0:k0+KC]^T
// W[o,c] = means[o, dest[o*IN_K + c] & 15] built on the fly in shared.
// grid = (OUT_N/OT, KSPLIT) = (16, 16), block = 256
// Register tile per thread: 4 batch x 8 out, k packed in f32x2 pairs.
// (Design frozen since R4 pending first successful bench.)
// ---------------------------------------------------------------------------
__global__ __launch_bounds__(256, 2)
void sic_gemm_partial(const float* __restrict__ x,
                      const float* __restrict__ means,
                      const int*   __restrict__ dest)
{
    __shared__ __align__(16) float means_s[OT * GMAX];   // 1024 floats
    __shared__ __align__(16) float x_s[BATCH * XPAD];    // 128*36 (18 KB)
    __shared__ __align__(16) float w_s[OT * XPAD];       // 64*36  (9.2 KB)

    const int tid = threadIdx.x;
    const int o0  = blockIdx.x * OT;
    const int k0  = blockIdx.y * KC;

    // per-block means LUT: 1024 entries, 256 threads
    #pragma unroll
    for (int v = 0; v < 4; v++)
        means_s[tid + v * 256] = means[o0 * GMAX + tid + v * 256];

    const int tb = tid & 31;    // batch lane   (covers b = tb + 32*i, i<4)
    const int to = tid >> 5;    // warp id      (covers o = to + 8*j, j<8)

    u64 acc[4][8];
    #pragma unroll
    for (int i = 0; i < 4; i++)
        #pragma unroll
        for (int j = 0; j < 8; j++)
            acc[i][j] = 0ull;

    for (int ks = 0; ks < KC; ks += KS) {
        // ---- issue this stage's global loads BEFORE the barrier:
        //      LDG latency overlaps barrier wait + other warps' compute ----
        float4 xr[4];
        #pragma unroll
        for (int i = 0; i < 4; i++) {
            int s = tid + i * 256;
            xr[i] = *reinterpret_cast<const float4*>(
                &x[(s >> 3) * IN_K + k0 + ks + (s & 7) * 4]);
        }
        int4 dr[2];
        #pragma unroll
        for (int v = 0; v < 2; v++) {
            int s = tid + v * 256;
            dr[v] = *reinterpret_cast<const int4*>(
                &dest[(o0 + (s >> 3)) * IN_K + k0 + ks + (s & 7) * 4]);
        }

        __syncthreads();   // protects x_s/w_s reuse; 1st iter: means_s barrier

        // ---- store x tile: 128 rows x 32 cols ----
        #pragma unroll
        for (int i = 0; i < 4; i++) {
            int s = tid + i * 256;
            *reinterpret_cast<float4*>(&x_s[(s >> 3) * XPAD + (s & 7) * 4]) = xr[i];
        }
        // ---- build w tile: 64 rows x 32 cols via 16-entry LUT ----
        #pragma unroll
        for (int v = 0; v < 2; v++) {
            int s = tid + v * 256;
            int o = s >> 3;
            const float* lut = &means_s[o * GMAX];
            float4 w;
            w.x = lut[dr[v].x & 15];
            w.y = lut[dr[v].y & 15];
            w.z = lut[dr[v].z & 15];
            w.w = lut[dr[v].w & 15];
            *reinterpret_cast<float4*>(&w_s[o * XPAD + (s & 7) * 4]) = w;
        }
        __syncthreads();

        // ---- compute: 4b x 8o tile, k by 4 (2 f32x2 pairs) ----
        #pragma unroll
        for (int kk = 0; kk < KS; kk += 4) {
            ulonglong2 xv[4];
            #pragma unroll
            for (int i = 0; i < 4; i++)
                xv[i] = *reinterpret_cast<const ulonglong2*>(
                    &x_s[(tb + 32 * i) * XPAD + kk]);
            #pragma unroll
            for (int j = 0; j < 8; j++) {
                ulonglong2 wv = *reinterpret_cast<const ulonglong2*>(
                    &w_s[(to + 8 * j) * XPAD + kk]);
                #pragma unroll
                for (int i = 0; i < 4; i++) {
                    acc[i][j] = ffma2(xv[i].x, wv.x, acc[i][j]);
                    acc[i][j] = ffma2(xv[i].y, wv.y, acc[i][j]);
                }
            }
        }
    }

    // ---- epilogue: two passes staged through x_s (64 rows x 65 each);
    //      acc[2p+i][j] holds global row b = 64p + tb + 32i ----
    float* dst = g_scratch + blockIdx.y * (BATCH * OUT_N);
    float* res = x_s;   // 64*65 = 4160 floats <= 4608
    #pragma unroll
    for (int p = 0; p < 2; p++) {
        __syncthreads();
        #pragma unroll
        for (int i = 0; i < 2; i++)
            #pragma unroll
            for (int j = 0; j < 8; j++)
                res[(tb + 32 * i) * RPAD + (to + 8 * j)] =
                    f32x2_hsum(acc[2 * p + i][j]);
        __syncthreads();
        #pragma unroll
        for (int v = 0; v < 4; v++) {
            int s  = tid + v * 256;          // float4 slot 0..1023
            int bl = s >> 4;                 // 16 float4 per 64-col row
            int ol = (s & 15) * 4;
            float4 r;
            r.x = res[bl * RPAD + ol + 0];
            r.y = res[bl * RPAD + ol + 1];
            r.z = res[bl * RPAD + ol + 2];
            r.w = res[bl * RPAD + ol + 3];
            *reinterpret_cast<float4*>(
                &dst[(64 * p + bl) * OUT_N + o0 + ol]) = r;
        }
    }
}

// ---------------------------------------------------------------------------
// Kernel B: reduce KSPLIT partials + bias (float4).  grid = 128, block = 256
// ---------------------------------------------------------------------------
__global__ __launch_bounds__(256)
void sic_reduce(const float* __restrict__ bias, float* __restrict__ out)
{
    int q = blockIdx.x * 256 + threadIdx.x;       // float4 slot 0..32767
    int f = q * 4;
    float4 s = *reinterpret_cast<const float4*>(&bias[f & (OUT_N - 1)]);
    #pragma unroll
    for (int i = 0; i < KSPLIT; i++) {
        float4 p = *reinterpret_cast<const float4*>(
            &g_scratch[i * (BATCH * OUT_N) + f]);
        s.x += p.x; s.y += p.y; s.z += p.z; s.w += p.w;
    }
    *reinterpret_cast<float4*>(&out[f]) = s;
}

// ---------------------------------------------------------------------------
// launch: inputs per metadata order: x, means, bias, col_idx, dest
// ---------------------------------------------------------------------------
extern "C" void kernel_launch(void* const* d_in, const int* in_sizes, int n_in,
                              void* d_out, int out_size)
{
    const float* x     = (const float*)d_in[0];   // [128,1024]
    const float* means = (const float*)d_in[1];   // [1024,16]
    const float* bias  = (const float*)d_in[2];   // [1024]
    // d_in[3] = col_idx: tile(arange(IN)) -> identity gather, unused
    const int*   dest  = (const int*)d_in[4];     // [1024*1024]
    float* out = (float*)d_out;                   // [128,1024]

    dim3 gridA(OUT_N / OT, KSPLIT);
    sic_gemm_partial<<<gridA, 256>>>(x, means, dest);
    sic_reduce<<<(BATCH * OUT_N) / (256 * 4), 256>>>(bias, out);
}

// round 14
// speedup vs baseline: 1.0019x; 1.0019x over previous
#include <cuda_runtime.h>
#include <cuda_bf16.h>

typedef unsigned long long u64;

#define BATCH  128
#define IN_K   1024
#define OUT_N  1024
#define GMAX   16

#define OT     64     // output rows per block tile
#define KSPLIT 16     // k-splits
#define KC     (IN_K / KSPLIT)   // 64 k per block
#define KS     32     // k per shared stage
#define XPAD   36     // padded row stride (floats): conflict-free LDS.128
#define RPAD   65     // epilogue staging stride (64 cols + 1)

// split-K partial sums: [KSPLIT][BATCH][OUT_N]  (8 MB, static device scratch)
__device__ float g_scratch[KSPLIT * BATCH * OUT_N];

__device__ __forceinline__ u64 ffma2(u64 a, u64 b, u64 c) {
    u64 d;
    asm("fma.rn.f32x2 %0, %1, %2, %3;" : "=l"(d) : "l"(a), "l"(b), "l"(c));
    return d;
}

__device__ __forceinline__ float f32x2_hsum(u64 v) {
    float lo = __uint_as_float((unsigned)(v & 0xffffffffull));
    float hi = __uint_as_float((unsigned)(v >> 32));
    return lo + hi;
}

// ---------------------------------------------------------------------------
// Kernel A: partial GEMM. y_partial = x[:, k0:k0+KC] @ W[:, k0:k0+KC]^T
// W[o,c] = means[o, dest[o*IN_K + c] & 15] built on the fly in shared.
// grid = (OUT_N/OT, KSPLIT) = (16, 16), block = 256
// Register tile per thread: 4 batch x 8 out, k packed in f32x2 pairs.
// (FROZEN: unchanged from the 17.1us passing version for clean attribution.)
// ---------------------------------------------------------------------------
__global__ __launch_bounds__(256, 2)
void sic_gemm_partial(const float* __restrict__ x,
                      const float* __restrict__ means,
                      const int*   __restrict__ dest)
{
    __shared__ __align__(16) float means_s[OT * GMAX];   // 1024 floats
    __shared__ __align__(16) float x_s[BATCH * XPAD];    // 128*36 (18 KB)
    __shared__ __align__(16) float w_s[OT * XPAD];       // 64*36  (9.2 KB)

    const int tid = threadIdx.x;
    const int o0  = blockIdx.x * OT;
    const int k0  = blockIdx.y * KC;

    // per-block means LUT: 1024 entries, 256 threads
    #pragma unroll
    for (int v = 0; v < 4; v++)
        means_s[tid + v * 256] = means[o0 * GMAX + tid + v * 256];

    const int tb = tid & 31;    // batch lane   (covers b = tb + 32*i, i<4)
    const int to = tid >> 5;    // warp id      (covers o = to + 8*j, j<8)

    u64 acc[4][8];
    #pragma unroll
    for (int i = 0; i < 4; i++)
        #pragma unroll
        for (int j = 0; j < 8; j++)
            acc[i][j] = 0ull;

    for (int ks = 0; ks < KC; ks += KS) {
        // ---- issue this stage's global loads BEFORE the barrier ----
        float4 xr[4];
        #pragma unroll
        for (int i = 0; i < 4; i++) {
            int s = tid + i * 256;
            xr[i] = *reinterpret_cast<const float4*>(
                &x[(s >> 3) * IN_K + k0 + ks + (s & 7) * 4]);
        }
        int4 dr[2];
        #pragma unroll
        for (int v = 0; v < 2; v++) {
            int s = tid + v * 256;
            dr[v] = *reinterpret_cast<const int4*>(
                &dest[(o0 + (s >> 3)) * IN_K + k0 + ks + (s & 7) * 4]);
        }

        __syncthreads();   // protects x_s/w_s reuse; 1st iter: means_s barrier

        // ---- store x tile: 128 rows x 32 cols ----
        #pragma unroll
        for (int i = 0; i < 4; i++) {
            int s = tid + i * 256;
            *reinterpret_cast<float4*>(&x_s[(s >> 3) * XPAD + (s & 7) * 4]) = xr[i];
        }
        // ---- build w tile: 64 rows x 32 cols via 16-entry LUT ----
        #pragma unroll
        for (int v = 0; v < 2; v++) {
            int s = tid + v * 256;
            int o = s >> 3;
            const float* lut = &means_s[o * GMAX];
            float4 w;
            w.x = lut[dr[v].x & 15];
            w.y = lut[dr[v].y & 15];
            w.z = lut[dr[v].z & 15];
            w.w = lut[dr[v].w & 15];
            *reinterpret_cast<float4*>(&w_s[o * XPAD + (s & 7) * 4]) = w;
        }
        __syncthreads();

        // ---- compute: 4b x 8o tile, k by 4 (2 f32x2 pairs) ----
        #pragma unroll
        for (int kk = 0; kk < KS; kk += 4) {
            ulonglong2 xv[4];
            #pragma unroll
            for (int i = 0; i < 4; i++)
                xv[i] = *reinterpret_cast<const ulonglong2*>(
                    &x_s[(tb + 32 * i) * XPAD + kk]);
            #pragma unroll
            for (int j = 0; j < 8; j++) {
                ulonglong2 wv = *reinterpret_cast<const ulonglong2*>(
                    &w_s[(to + 8 * j) * XPAD + kk]);
                #pragma unroll
                for (int i = 0; i < 4; i++) {
                    acc[i][j] = ffma2(xv[i].x, wv.x, acc[i][j]);
                    acc[i][j] = ffma2(xv[i].y, wv.y, acc[i][j]);
                }
            }
        }
    }

    // ---- epilogue: two passes staged through x_s (64 rows x 65 each);
    //      acc[2p+i][j] holds global row b = 64p + tb + 32i ----
    float* dst = g_scratch + blockIdx.y * (BATCH * OUT_N);
    float* res = x_s;   // 64*65 = 4160 floats <= 4608
    #pragma unroll
    for (int p = 0; p < 2; p++) {
        __syncthreads();
        #pragma unroll
        for (int i = 0; i < 2; i++)
            #pragma unroll
            for (int j = 0; j < 8; j++)
                res[(tb + 32 * i) * RPAD + (to + 8 * j)] =
                    f32x2_hsum(acc[2 * p + i][j]);
        __syncthreads();
        #pragma unroll
        for (int v = 0; v < 4; v++) {
            int s  = tid + v * 256;          // float4 slot 0..1023
            int bl = s >> 4;                 // 16 float4 per 64-col row
            int ol = (s & 15) * 4;
            float4 r;
            r.x = res[bl * RPAD + ol + 0];
            r.y = res[bl * RPAD + ol + 1];
            r.z = res[bl * RPAD + ol + 2];
            r.w = res[bl * RPAD + ol + 3];
            *reinterpret_cast<float4*>(
                &dst[(64 * p + bl) * OUT_N + o0 + ol]) = r;
        }
    }
}

// ---------------------------------------------------------------------------
// Kernel B: reduce KSPLIT partials + bias.
// Occupancy fix (untested, from R12 post-mortem): scalar lanes,
// grid = 512 x 256 (4096 warps chip-wide vs 1024; measured 12.4% occ /
// 15.9% DRAM -> latency-bound). 16 independent coalesced LDGs per thread.
// ---------------------------------------------------------------------------
__global__ __launch_bounds__(256)
void sic_reduce(const float* __restrict__ bias, float* __restrict__ out)
{
    int t = blockIdx.x * 256 + threadIdx.x;       // 0 .. BATCH*OUT_N-1
    float p[KSPLIT];
    #pragma unroll
    for (int i = 0; i < KSPLIT; i++)              // 16 independent LDGs
        p[i] = g_scratch[i * (BATCH * OUT_N) + t];
    float s = __ldg(&bias[t & (OUT_N - 1)]);
    #pragma unroll
    for (int i = 0; i < KSPLIT; i++)
        s += p[i];
    out[t] = s;
}

// ---------------------------------------------------------------------------
// launch: inputs per metadata order: x, means, bias, col_idx, dest
// ---------------------------------------------------------------------------
extern "C" void kernel_launch(void* const* d_in, const int* in_sizes, int n_in,
                              void* d_out, int out_size)
{
    const float* x     = (const float*)d_in[0];   // [128,1024]
    const float* means = (const float*)d_in[1];   // [1024,16]
    const float* bias  = (const float*)d_in[2];   // [1024]
    // d_in[3] = col_idx: tile(arange(IN)) -> identity gather, unused
    const int*   dest  = (const int*)d_in[4];     // [1024*1024]
    float* out = (float*)d_out;                   // [128,1024]

    dim3 gridA(OUT_N / OT, KSPLIT);
    sic_gemm_partial<<<gridA, 256>>>(x, means, dest);
    sic_reduce<<<(BATCH * OUT_N) / 256, 256>>>(bias, out);
}